// round 1
// baseline (speedup 1.0000x reference)
#include <cuda_runtime.h>
#include <math.h>

// Problem constants (fixed shapes for this dataset)
#define I_DIM 32
#define J_DIM 32
#define S_DIM 256
#define H_DIM 768
#define SBLK  64     // s-rows per block
#define BK    32     // h-tile depth
#define NTHREADS 256

// Scratch (no allocations allowed -> __device__ globals)
__device__ float g_qn[I_DIM * S_DIM * H_DIM];
__device__ float g_kn[J_DIM * S_DIM * H_DIM];
__device__ float g_part[I_DIM * J_DIM * (S_DIM / SBLK)];

// ---------------------------------------------------------------------------
// L2-normalize rows of [rows, 768]. One block per row, 256 threads, 3 elems each.
// which==0 -> g_qn, which==1 -> g_kn
// ---------------------------------------------------------------------------
__global__ void normalize_kernel(const float* __restrict__ in, int which) {
    const int row = blockIdx.x;
    const float* x = in + (size_t)row * H_DIM;
    float* out = (which ? g_kn : g_qn) + (size_t)row * H_DIM;

    float v0 = x[threadIdx.x];
    float v1 = x[threadIdx.x + 256];
    float v2 = x[threadIdx.x + 512];
    float s = v0 * v0 + v1 * v1 + v2 * v2;

    #pragma unroll
    for (int o = 16; o; o >>= 1) s += __shfl_xor_sync(0xffffffffu, s, o);

    __shared__ float red[8];
    __shared__ float inv;
    if ((threadIdx.x & 31) == 0) red[threadIdx.x >> 5] = s;
    __syncthreads();
    if (threadIdx.x == 0) {
        float t = 0.0f;
        #pragma unroll
        for (int w = 0; w < 8; w++) t += red[w];
        inv = 1.0f / fmaxf(sqrtf(t), 1e-12f);
    }
    __syncthreads();
    const float iv = inv;
    out[threadIdx.x]       = v0 * iv;
    out[threadIdx.x + 256] = v1 * iv;
    out[threadIdx.x + 512] = v2 * iv;
}

// ---------------------------------------------------------------------------
// Fused pair kernel: block = (s-slab sb, j, i).
// Computes C[64,256] = Qn_i[s0:s0+64,:] @ Kn_j^T in registers (8x8 per thread),
// then fused decay/mask/softmax/score epilogue. Writes deterministic partial.
// Thread map: warp ty in [0,8) owns s rows ty*8..ty*8+7; lane tx owns t cols
// tx*8..tx*8+7  -> row reductions are pure warp shuffles.
// ---------------------------------------------------------------------------
__global__ __launch_bounds__(NTHREADS, 2)
void pair_kernel(const float* __restrict__ q_mask, const float* __restrict__ k_mask,
                 const float* __restrict__ alpha_raw)
{
    const int sb = blockIdx.x;   // 0..3
    const int j  = blockIdx.y;
    const int i  = blockIdx.z;
    const int s0 = sb * SBLK;

    const int tid = threadIdx.x;
    const int ty  = tid >> 5;    // warp  -> s group
    const int tx  = tid & 31;    // lane  -> t group

    __shared__ float Qs[BK][SBLK + 1];    // +1 pad: conflict-free transpose stores
    __shared__ float Ks[BK][S_DIM + 1];
    __shared__ float qm_s[SBLK];
    __shared__ float km_s[S_DIM];
    __shared__ float dtab[S_DIM];
    __shared__ float warpsum[8];
    __shared__ float qsum_sh;

    // alpha = softplus(alpha_raw), numerically stable
    const float araw  = __ldg(alpha_raw);
    const float alpha = fmaxf(araw, 0.0f) + log1pf(expf(-fabsf(araw)));

    // masks, decay LUT, q_mask row sum
    if (tid < SBLK) qm_s[tid] = q_mask[i * S_DIM + s0 + tid];
    km_s[tid] = k_mask[j * S_DIM + tid];
    dtab[tid] = expf(-alpha * (float)tid);
    float qv = q_mask[i * S_DIM + tid];
    #pragma unroll
    for (int o = 16; o; o >>= 1) qv += __shfl_xor_sync(0xffffffffu, qv, o);
    if (tid == 0) qsum_sh = 0.0f;
    __syncthreads();
    if (tx == 0) atomicAdd(&qsum_sh, qv);   // 8 adds, resolved before epilogue sync

    float acc[8][8];
    #pragma unroll
    for (int a = 0; a < 8; a++)
        #pragma unroll
        for (int b = 0; b < 8; b++) acc[a][b] = 0.0f;

    const float* qbase = g_qn + ((size_t)i * S_DIM + s0) * H_DIM;
    const float* kbase = g_kn + (size_t)j * S_DIM * H_DIM;

    for (int h0 = 0; h0 < H_DIM; h0 += BK) {
        __syncthreads();
        // Q tile 64x32 -> Qs[k][s] (transpose); 512 float4 items, 2/thread
        #pragma unroll
        for (int it = 0; it < 2; it++) {
            const int item = tid + it * NTHREADS;
            const int s  = item >> 3;
            const int k4 = item & 7;
            float4 v = *reinterpret_cast<const float4*>(qbase + (size_t)s * H_DIM + h0 + k4 * 4);
            Qs[k4 * 4 + 0][s] = v.x;
            Qs[k4 * 4 + 1][s] = v.y;
            Qs[k4 * 4 + 2][s] = v.z;
            Qs[k4 * 4 + 3][s] = v.w;
        }
        // K tile 256x32 -> Ks[k][t]; 2048 items, 8/thread
        #pragma unroll
        for (int it = 0; it < 8; it++) {
            const int item = tid + it * NTHREADS;
            const int t  = item >> 3;
            const int k4 = item & 7;
            float4 v = *reinterpret_cast<const float4*>(kbase + (size_t)t * H_DIM + h0 + k4 * 4);
            Ks[k4 * 4 + 0][t] = v.x;
            Ks[k4 * 4 + 1][t] = v.y;
            Ks[k4 * 4 + 2][t] = v.z;
            Ks[k4 * 4 + 3][t] = v.w;
        }
        __syncthreads();

        #pragma unroll
        for (int k = 0; k < BK; k++) {
            float qr[8], kr[8];
            #pragma unroll
            for (int a = 0; a < 8; a++) qr[a] = Qs[k][ty * 8 + a];   // warp broadcast
            #pragma unroll
            for (int b = 0; b < 8; b++) kr[b] = Ks[k][tx * 8 + b];
            #pragma unroll
            for (int a = 0; a < 8; a++)
                #pragma unroll
                for (int b = 0; b < 8; b++)
                    acc[a][b] = fmaf(qr[a], kr[b], acc[a][b]);
        }
    }
    __syncthreads();   // acc done everywhere; qsum_sh final

    // Fused epilogue: per s-row softmax over t (warp-wide), score, accumulate.
    float part = 0.0f;
    #pragma unroll
    for (int a = 0; a < 8; a++) {
        const int s_local = ty * 8 + a;
        const int s_glob  = s0 + s_local;
        const float qm = qm_s[s_local];
        float lg[8];
        float mx = -3.0e38f;
        #pragma unroll
        for (int b = 0; b < 8; b++) {
            const int t = tx * 8 + b;
            const float km    = km_s[t];
            const float valid = qm * km;
            const float dec   = dtab[abs(s_glob - t)];
            const float lv    = acc[a][b] * dec * valid - (1.0f - valid) * 1e9f;
            lg[b] = lv;
            mx = fmaxf(mx, lv);
        }
        #pragma unroll
        for (int o = 16; o; o >>= 1) mx = fmaxf(mx, __shfl_xor_sync(0xffffffffu, mx, o));
        float se = 0.0f, sc = 0.0f;
        #pragma unroll
        for (int b = 0; b < 8; b++) {
            const float e = expf(lg[b] - mx);
            se += e;
            sc = fmaf(e, acc[a][b], sc);
        }
        #pragma unroll
        for (int o = 16; o; o >>= 1) {
            se += __shfl_xor_sync(0xffffffffu, se, o);
            sc += __shfl_xor_sync(0xffffffffu, sc, o);
        }
        part += (sc / se) * qm;
    }
    if (tx == 0) warpsum[ty] = part;
    __syncthreads();
    if (tid == 0) {
        float tot = 0.0f;
        #pragma unroll
        for (int w = 0; w < 8; w++) tot += warpsum[w];
        const float denom = fmaxf(qsum_sh, 1.0f);
        g_part[(i * J_DIM + j) * (S_DIM / SBLK) + sb] = tot / denom;
    }
}

// Deterministic final reduce of the 4 s-slab partials per (i,j).
__global__ void reduce_kernel(float* __restrict__ out) {
    const int idx = blockIdx.x * blockDim.x + threadIdx.x;
    if (idx < I_DIM * J_DIM) {
        const float* p = &g_part[idx * (S_DIM / SBLK)];
        out[idx] = (p[0] + p[1]) + (p[2] + p[3]);
    }
}

extern "C" void kernel_launch(void* const* d_in, const int* in_sizes, int n_in,
                              void* d_out, int out_size) {
    const float* q  = (const float*)d_in[0];  // [32,256,768]
    const float* k  = (const float*)d_in[1];  // [32,256,768]
    const float* qm = (const float*)d_in[2];  // [32,256]
    const float* km = (const float*)d_in[3];  // [32,256]
    const float* ar = (const float*)d_in[4];  // scalar
    float* out = (float*)d_out;               // [32,32]

    normalize_kernel<<<I_DIM * S_DIM, 256>>>(q, 0);
    normalize_kernel<<<J_DIM * S_DIM, 256>>>(k, 1);

    dim3 grid(S_DIM / SBLK, J_DIM, I_DIM);
    pair_kernel<<<grid, NTHREADS>>>(qm, km, ar);

    reduce_kernel<<<(I_DIM * J_DIM + 255) / 256, 256>>>(out);
}

// round 3
// speedup vs baseline: 4.6854x; 4.6854x over previous
#include <cuda_runtime.h>
#include <cuda_fp16.h>
#include <math.h>
#include <stdint.h>

#define I_DIM 32
#define J_DIM 32
#define S_DIM 256
#define H_DIM 768
#define NTH 256
#define NCHUNK 12          // 768 / 64

// smem byte offsets (from 128B-aligned base)
#define STAGE_STRIDE 81920
#define OFF_Q   0
#define OFF_KH  16384
#define OFF_KL  49152
#define OFF_DTAB 163840
#define OFF_KM   164864
#define OFF_QM   165888
#define OFF_PM   166400
#define OFF_PSE  167424
#define OFF_PSC  168448
#define OFF_RED  169472
#define SMEM_DYN (169600 + 128)

// ----------------------------------------------------------- device scratch
__device__ __align__(16) __half g_qh[I_DIM * S_DIM * H_DIM];
__device__ __align__(16) __half g_kh[J_DIM * S_DIM * H_DIM];
__device__ __align__(16) __half g_kl[J_DIM * S_DIM * H_DIM];
__device__ float g_part[I_DIM * J_DIM * 2];

// --------------------------------------------------------------- asm helpers
__device__ __forceinline__ uint32_t smem_u32(const void* p) {
    uint32_t a;
    asm("{ .reg .u64 t; cvta.to.shared.u64 t, %1; cvt.u32.u64 %0, t; }" : "=r"(a) : "l"(p));
    return a;
}
__device__ __forceinline__ void cp16(uint32_t s, const void* g) {
    asm volatile("{ .reg .u64 gg; cvta.to.global.u64 gg, %1; cp.async.cg.shared.global [%0], [gg], 16; }"
                 :: "r"(s), "l"(g));
}
#define CP_COMMIT() asm volatile("cp.async.commit_group;" ::: "memory")
#define CP_WAIT(N)  asm volatile("cp.async.wait_group %0;" :: "n"(N) : "memory")

__device__ __forceinline__ void ldsm4(uint32_t* A, uint32_t addr) {
    asm volatile("ldmatrix.sync.aligned.m8n8.x4.shared.b16 {%0,%1,%2,%3}, [%4];"
                 : "=r"(A[0]), "=r"(A[1]), "=r"(A[2]), "=r"(A[3]) : "r"(addr));
}
__device__ __forceinline__ void lds32(uint32_t& v, uint32_t addr) {
    asm volatile("ld.shared.b32 %0, [%1];" : "=r"(v) : "r"(addr));
}
__device__ __forceinline__ void mma16816(float* c, const uint32_t* a, uint32_t b0, uint32_t b1) {
    asm volatile("mma.sync.aligned.m16n8k16.row.col.f32.f16.f16.f32 "
                 "{%0,%1,%2,%3}, {%4,%5,%6,%7}, {%8,%9}, {%0,%1,%2,%3};"
                 : "+f"(c[0]), "+f"(c[1]), "+f"(c[2]), "+f"(c[3])
                 : "r"(a[0]), "r"(a[1]), "r"(a[2]), "r"(a[3]), "r"(b0), "r"(b1));
}

// ------------------------------------------------- normalize + fp16 hi/lo split
__global__ void norm_split_kernel(const float* __restrict__ in, int which) {
    const int row = blockIdx.x;
    const float* x = in + (size_t)row * H_DIM;
    __half* hi = (which ? g_kh : g_qh) + (size_t)row * H_DIM;
    __half* lo = which ? (g_kl + (size_t)row * H_DIM) : nullptr;

    float v0 = x[threadIdx.x], v1 = x[threadIdx.x + 256], v2 = x[threadIdx.x + 512];
    float s = v0 * v0 + v1 * v1 + v2 * v2;
    #pragma unroll
    for (int o = 16; o; o >>= 1) s += __shfl_xor_sync(0xffffffffu, s, o);

    __shared__ float red[8];
    __shared__ float inv;
    if ((threadIdx.x & 31) == 0) red[threadIdx.x >> 5] = s;
    __syncthreads();
    if (threadIdx.x == 0) {
        float t = 0.f;
        #pragma unroll
        for (int w = 0; w < 8; w++) t += red[w];
        inv = 1.0f / fmaxf(sqrtf(t), 1e-12f);
    }
    __syncthreads();
    const float iv = inv;
    #pragma unroll
    for (int e = 0; e < 3; e++) {
        const int idx = threadIdx.x + e * 256;
        const float f = (e == 0 ? v0 : (e == 1 ? v1 : v2)) * iv;
        const __half h = __float2half(f);
        hi[idx] = h;
        if (lo) lo[idx] = __float2half(f - __half2float(h));
    }
}

// ----------------------------------------------------------- stage loader
// Tile rows have 64 halves (128B = 8 x 16B groups), swizzle: group ^= row&7.
__device__ __forceinline__ void load_stage(uint32_t qdst, uint32_t khdst, uint32_t kldst,
                                           const char* qsrc, const char* khsrc, const char* klsrc,
                                           int tid) {
    #pragma unroll
    for (int it = 0; it < 4; it++) {               // Q: 128 rows
        const int idx = tid + it * NTH;
        const int row = idx >> 3, g = idx & 7, gs = g ^ (row & 7);
        cp16(qdst + row * 128 + gs * 16, qsrc + (size_t)row * 1536 + g * 16);
    }
    #pragma unroll
    for (int it = 0; it < 8; it++) {               // KH: 256 rows
        const int idx = tid + it * NTH;
        const int row = idx >> 3, g = idx & 7, gs = g ^ (row & 7);
        cp16(khdst + row * 128 + gs * 16, khsrc + (size_t)row * 1536 + g * 16);
    }
    #pragma unroll
    for (int it = 0; it < 8; it++) {               // KL: 256 rows
        const int idx = tid + it * NTH;
        const int row = idx >> 3, g = idx & 7, gs = g ^ (row & 7);
        cp16(kldst + row * 128 + gs * 16, klsrc + (size_t)row * 1536 + g * 16);
    }
}

// ----------------------------------------------------------- chunk compute
__device__ __forceinline__ void compute_chunk(
    uint32_t qs, uint32_t khs, uint32_t kls, float acc[2][16][4],
    uint32_t arow_off0, uint32_t hb, uint32_t l7,
    uint32_t brow_off, uint32_t gid, uint32_t tig)
{
    #pragma unroll
    for (int ks = 0; ks < 4; ks++) {
        uint32_t A[2][4];
        #pragma unroll
        for (int mf = 0; mf < 2; mf++) {
            const uint32_t agrp = (2u * ks + hb) ^ l7;
            ldsm4(A[mf], qs + arow_off0 + mf * 2048 + (agrp << 4));
        }
        const uint32_t g0 = ((2u * ks) ^ gid) << 4;
        const uint32_t g1 = ((2u * ks + 1u) ^ gid) << 4;
        const uint32_t bh0 = khs + brow_off + g0 + 4 * tig;
        const uint32_t bh1 = khs + brow_off + g1 + 4 * tig;
        const uint32_t bl0 = kls + brow_off + g0 + 4 * tig;
        const uint32_t bl1 = kls + brow_off + g1 + 4 * tig;
        #pragma unroll
        for (int nf = 0; nf < 16; nf++) {
            uint32_t b0, b1;
            lds32(b0, bh0 + nf * 1024); lds32(b1, bh1 + nf * 1024);
            mma16816(acc[0][nf], A[0], b0, b1);
            mma16816(acc[1][nf], A[1], b0, b1);
            lds32(b0, bl0 + nf * 1024); lds32(b1, bl1 + nf * 1024);
            mma16816(acc[0][nf], A[0], b0, b1);
            mma16816(acc[1][nf], A[1], b0, b1);
        }
    }
}

// ------------------------------------------------ fused pair GEMM + epilogue
__global__ __launch_bounds__(NTH, 1)
void pair_kernel(const float* __restrict__ q_mask, const float* __restrict__ k_mask,
                 const float* __restrict__ alpha_raw)
{
    extern __shared__ char smraw[];
    const uint32_t rawu = smem_u32(smraw);
    const uint32_t pad = (128u - (rawu & 127u)) & 127u;
    char* sb = smraw + pad;
    const uint32_t sbu = rawu + pad;

    const int mtile = blockIdx.x;
    const int j = blockIdx.y;
    const int i = blockIdx.z;
    const int tid = threadIdx.x;
    const int wid = tid >> 5;
    const int lane = tid & 31;
    const int warp_m = wid & 3;        // 4 m-warps (32 s-rows each)
    const int warp_n = wid >> 2;       // 2 n-warps (128 t-cols each)
    const uint32_t gid = lane >> 2, tig = lane & 3;
    const uint32_t hb = lane >> 4, l7 = lane & 7;

    float* dtab = (float*)(sb + OFF_DTAB);
    float* km_s = (float*)(sb + OFF_KM);
    float* qm_s = (float*)(sb + OFF_QM);
    float* pm   = (float*)(sb + OFF_PM);
    float* pse  = (float*)(sb + OFF_PSE);
    float* psc  = (float*)(sb + OFF_PSC);
    float* redw = (float*)(sb + OFF_RED);

    const float araw  = __ldg(alpha_raw);
    const float alpha = fmaxf(araw, 0.0f) + log1pf(expf(-fabsf(araw)));
    dtab[tid] = expf(-alpha * (float)tid);
    km_s[tid] = k_mask[j * S_DIM + tid];
    if (tid < 128) qm_s[tid] = q_mask[i * S_DIM + mtile * 128 + tid];

    const char* qsrc  = (const char*)(g_qh + ((size_t)i * S_DIM + mtile * 128) * H_DIM);
    const char* khsrc = (const char*)(g_kh + (size_t)j * S_DIM * H_DIM);
    const char* klsrc = (const char*)(g_kl + (size_t)j * S_DIM * H_DIM);

    // prologue: chunks 0,1 into stages 0,1
    load_stage(sbu + OFF_Q, sbu + OFF_KH, sbu + OFF_KL, qsrc, khsrc, klsrc, tid);
    CP_COMMIT();
    load_stage(sbu + STAGE_STRIDE + OFF_Q, sbu + STAGE_STRIDE + OFF_KH, sbu + STAGE_STRIDE + OFF_KL,
               qsrc + 128, khsrc + 128, klsrc + 128, tid);
    CP_COMMIT();

    float acc[2][16][4];
    #pragma unroll
    for (int a = 0; a < 2; a++)
        #pragma unroll
        for (int b = 0; b < 16; b++)
            #pragma unroll
            for (int c = 0; c < 4; c++) acc[a][b][c] = 0.0f;

    const uint32_t arow_off0 = (warp_m * 32 + (lane & 15)) * 128;
    const uint32_t brow_off  = (warp_n * 128 + gid) * 128;

    for (int c = 0; c < NCHUNK; c++) {
        if (c < NCHUNK - 1) CP_WAIT(1); else CP_WAIT(0);
        __syncthreads();
        const uint32_t st = sbu + (uint32_t)(c & 1) * STAGE_STRIDE;
        compute_chunk(st + OFF_Q, st + OFF_KH, st + OFF_KL, acc,
                      arow_off0, hb, l7, brow_off, gid, tig);
        if (c + 2 < NCHUNK) {
            __syncthreads();
            const int boff = (c + 2) * 128;
            load_stage(st + OFF_Q, st + OFF_KH, st + OFF_KL,
                       qsrc + boff, khsrc + boff, klsrc + boff, tid);
            CP_COMMIT();
        }
    }

    // ---------------- epilogue: per-row softmax over t ----------------
    #pragma unroll
    for (int mf = 0; mf < 2; mf++) {
        #pragma unroll
        for (int h = 0; h < 2; h++) {
            const int row_local = warp_m * 32 + mf * 16 + h * 8 + (int)gid;
            const int s_glob = mtile * 128 + row_local;
            const float qmr = qm_s[row_local];

            float lg[32];
            float mx = -3.0e38f;
            #pragma unroll
            for (int nf = 0; nf < 16; nf++) {
                #pragma unroll
                for (int dc = 0; dc < 2; dc++) {
                    const int t = warp_n * 128 + nf * 8 + 2 * (int)tig + dc;
                    const float v = acc[mf][nf][h * 2 + dc];
                    const float valid = qmr * km_s[t];
                    int d = s_glob - t; d = d < 0 ? -d : d;
                    const float lv = v * dtab[d] * valid - (1.0f - valid) * 1e9f;
                    lg[nf * 2 + dc] = lv;
                    mx = fmaxf(mx, lv);
                }
            }
            mx = fmaxf(mx, __shfl_xor_sync(0xffffffffu, mx, 1));
            mx = fmaxf(mx, __shfl_xor_sync(0xffffffffu, mx, 2));
            float se = 0.0f, sc = 0.0f;
            #pragma unroll
            for (int nf = 0; nf < 16; nf++) {
                #pragma unroll
                for (int dc = 0; dc < 2; dc++) {
                    const float e = __expf(lg[nf * 2 + dc] - mx);
                    se += e;
                    sc = fmaf(e, acc[mf][nf][h * 2 + dc], sc);
                }
            }
            #pragma unroll
            for (int o = 1; o <= 2; o <<= 1) {
                se += __shfl_xor_sync(0xffffffffu, se, o);
                sc += __shfl_xor_sync(0xffffffffu, sc, o);
            }
            if (tig == 0) {
                pm [warp_n * 128 + row_local] = mx;
                pse[warp_n * 128 + row_local] = se;
                psc[warp_n * 128 + row_local] = sc;
            }
        }
    }
    __syncthreads();

    float score = 0.0f;
    if (tid < 128) {
        const float m0 = pm[tid],        m1 = pm[128 + tid];
        const float nm = fmaxf(m0, m1);
        const float e0 = __expf(m0 - nm), e1 = __expf(m1 - nm);
        const float S  = pse[tid] * e0 + pse[128 + tid] * e1;
        const float C  = psc[tid] * e0 + psc[128 + tid] * e1;
        score = qm_s[tid] * (C / S);
    }
    #pragma unroll
    for (int o = 16; o; o >>= 1) score += __shfl_xor_sync(0xffffffffu, score, o);
    if (lane == 0) redw[wid] = score;
    __syncthreads();
    if (tid == 0) {
        float tot = 0.0f;
        #pragma unroll
        for (int w = 0; w < 8; w++) tot += redw[w];
        g_part[(i * J_DIM + j) * 2 + mtile] = tot;
    }
}

// --------------------------------------------------------------- final reduce
__global__ void reduce_kernel(const float* __restrict__ q_mask, float* __restrict__ out) {
    const int idx = blockIdx.x * blockDim.x + threadIdx.x;
    if (idx < I_DIM * J_DIM) {
        const int i = idx >> 5;
        float dn = 0.0f;
        #pragma unroll 8
        for (int s = 0; s < S_DIM; s++) dn += q_mask[i * S_DIM + s];
        dn = fmaxf(dn, 1.0f);
        out[idx] = (g_part[idx * 2] + g_part[idx * 2 + 1]) / dn;
    }
}

// -------------------------------------------------------------------- launch
extern "C" void kernel_launch(void* const* d_in, const int* in_sizes, int n_in,
                              void* d_out, int out_size) {
    const float* q  = (const float*)d_in[0];
    const float* k  = (const float*)d_in[1];
    const float* qm = (const float*)d_in[2];
    const float* km = (const float*)d_in[3];
    const float* ar = (const float*)d_in[4];
    float* out = (float*)d_out;

    norm_split_kernel<<<I_DIM * S_DIM, 256>>>(q, 0);
    norm_split_kernel<<<J_DIM * S_DIM, 256>>>(k, 1);

    static int smem_set = 0;
    if (!smem_set) {
        cudaFuncSetAttribute(pair_kernel, cudaFuncAttributeMaxDynamicSharedMemorySize, SMEM_DYN);
        smem_set = 1;
    }
    dim3 grid(2, J_DIM, I_DIM);
    pair_kernel<<<grid, NTH, SMEM_DYN>>>(qm, km, ar);

    reduce_kernel<<<4, 256>>>(qm, out);
}

// round 4
// speedup vs baseline: 7.8648x; 1.6786x over previous
#include <cuda_runtime.h>
#include <cuda_fp16.h>
#include <math.h>
#include <stdint.h>

#define I_DIM 32
#define J_DIM 32
#define S_DIM 256
#define H_DIM 768
#define NTH 256
#define NCHUNK 12          // 768 / 64
#define NSTAGE 3

// smem byte offsets (from 128B-aligned base)
#define STAGE_STRIDE 49152     // Q 16K + K 32K
#define OFF_Q   0
#define OFF_K   16384
#define OFF_DTAB 147456
#define OFF_KM   148480
#define OFF_QM   149504
#define OFF_PM   150016
#define OFF_PSE  151040
#define OFF_PSC  152064
#define OFF_RED  153088
#define SMEM_DYN (153216 + 128)

// ----------------------------------------------------------- device scratch
__device__ __align__(16) __half g_qh[I_DIM * S_DIM * H_DIM];
__device__ __align__(16) __half g_kh[J_DIM * S_DIM * H_DIM];
__device__ float g_part[I_DIM * J_DIM * 2];

// --------------------------------------------------------------- asm helpers
__device__ __forceinline__ uint32_t smem_u32(const void* p) {
    uint32_t a;
    asm("{ .reg .u64 t; cvta.to.shared.u64 t, %1; cvt.u32.u64 %0, t; }" : "=r"(a) : "l"(p));
    return a;
}
__device__ __forceinline__ void cp16(uint32_t s, const void* g) {
    asm volatile("{ .reg .u64 gg; cvta.to.global.u64 gg, %1; cp.async.cg.shared.global [%0], [gg], 16; }"
                 :: "r"(s), "l"(g));
}
#define CP_COMMIT() asm volatile("cp.async.commit_group;" ::: "memory")
#define CP_WAIT(N)  asm volatile("cp.async.wait_group %0;" :: "n"(N) : "memory")

__device__ __forceinline__ void ldsm4(uint32_t* A, uint32_t addr) {
    asm volatile("ldmatrix.sync.aligned.m8n8.x4.shared.b16 {%0,%1,%2,%3}, [%4];"
                 : "=r"(A[0]), "=r"(A[1]), "=r"(A[2]), "=r"(A[3]) : "r"(addr));
}
__device__ __forceinline__ void lds32(uint32_t& v, uint32_t addr) {
    asm volatile("ld.shared.b32 %0, [%1];" : "=r"(v) : "r"(addr));
}
__device__ __forceinline__ void mma16816(float* c, const uint32_t* a, uint32_t b0, uint32_t b1) {
    asm volatile("mma.sync.aligned.m16n8k16.row.col.f32.f16.f16.f32 "
                 "{%0,%1,%2,%3}, {%4,%5,%6,%7}, {%8,%9}, {%0,%1,%2,%3};"
                 : "+f"(c[0]), "+f"(c[1]), "+f"(c[2]), "+f"(c[3])
                 : "r"(a[0]), "r"(a[1]), "r"(a[2]), "r"(a[3]), "r"(b0), "r"(b1));
}

// ------------------------------------------------- normalize -> fp16
__global__ void norm_kernel(const float* __restrict__ in, int which) {
    const int row = blockIdx.x;
    const float* x = in + (size_t)row * H_DIM;
    __half* hi = (which ? g_kh : g_qh) + (size_t)row * H_DIM;

    float v0 = x[threadIdx.x], v1 = x[threadIdx.x + 256], v2 = x[threadIdx.x + 512];
    float s = v0 * v0 + v1 * v1 + v2 * v2;
    #pragma unroll
    for (int o = 16; o; o >>= 1) s += __shfl_xor_sync(0xffffffffu, s, o);

    __shared__ float red[8];
    __shared__ float inv;
    if ((threadIdx.x & 31) == 0) red[threadIdx.x >> 5] = s;
    __syncthreads();
    if (threadIdx.x == 0) {
        float t = 0.f;
        #pragma unroll
        for (int w = 0; w < 8; w++) t += red[w];
        inv = 1.0f / fmaxf(sqrtf(t), 1e-12f);
    }
    __syncthreads();
    const float iv = inv;
    hi[threadIdx.x]       = __float2half(v0 * iv);
    hi[threadIdx.x + 256] = __float2half(v1 * iv);
    hi[threadIdx.x + 512] = __float2half(v2 * iv);
}

// ----------------------------------------------------------- stage loader
// Tile rows have 64 halves (128B = 8 x 16B groups), swizzle: group ^= row&7.
__device__ __forceinline__ void load_stage(uint32_t qdst, uint32_t kdst,
                                           const char* qsrc, const char* ksrc, int tid) {
    #pragma unroll
    for (int it = 0; it < 4; it++) {               // Q: 128 rows
        const int idx = tid + it * NTH;
        const int row = idx >> 3, g = idx & 7, gs = g ^ (row & 7);
        cp16(qdst + row * 128 + gs * 16, qsrc + (size_t)row * 1536 + g * 16);
    }
    #pragma unroll
    for (int it = 0; it < 8; it++) {               // K: 256 rows
        const int idx = tid + it * NTH;
        const int row = idx >> 3, g = idx & 7, gs = g ^ (row & 7);
        cp16(kdst + row * 128 + gs * 16, ksrc + (size_t)row * 1536 + g * 16);
    }
}

// ----------------------------------------------------------- chunk compute
__device__ __forceinline__ void compute_chunk(
    uint32_t qs, uint32_t ks_, float acc[2][16][4],
    uint32_t arow_off0, uint32_t hb, uint32_t l7,
    uint32_t brow_off, uint32_t gid, uint32_t tig)
{
    #pragma unroll
    for (int ks = 0; ks < 4; ks++) {
        uint32_t A[2][4];
        #pragma unroll
        for (int mf = 0; mf < 2; mf++) {
            const uint32_t agrp = (2u * ks + hb) ^ l7;
            ldsm4(A[mf], qs + arow_off0 + mf * 2048 + (agrp << 4));
        }
        const uint32_t g0 = ((2u * ks) ^ gid) << 4;
        const uint32_t g1 = ((2u * ks + 1u) ^ gid) << 4;
        const uint32_t b0a = ks_ + brow_off + g0 + 4 * tig;
        const uint32_t b1a = ks_ + brow_off + g1 + 4 * tig;
        #pragma unroll
        for (int nf = 0; nf < 16; nf++) {
            uint32_t b0, b1;
            lds32(b0, b0a + nf * 1024); lds32(b1, b1a + nf * 1024);
            mma16816(acc[0][nf], A[0], b0, b1);
            mma16816(acc[1][nf], A[1], b0, b1);
        }
    }
}

// ------------------------------------------------ fused pair GEMM + epilogue
__global__ __launch_bounds__(NTH, 1)
void pair_kernel(const float* __restrict__ q_mask, const float* __restrict__ k_mask,
                 const float* __restrict__ alpha_raw)
{
    extern __shared__ char smraw[];
    const uint32_t rawu = smem_u32(smraw);
    const uint32_t pad = (128u - (rawu & 127u)) & 127u;
    char* sb = smraw + pad;
    const uint32_t sbu = rawu + pad;

    const int mtile = blockIdx.x;
    const int j = blockIdx.y;
    const int i = blockIdx.z;
    const int tid = threadIdx.x;
    const int wid = tid >> 5;
    const int lane = tid & 31;
    const int warp_m = wid & 3;        // 4 m-warps (32 s-rows each)
    const int warp_n = wid >> 2;       // 2 n-warps (128 t-cols each)
    const uint32_t gid = lane >> 2, tig = lane & 3;
    const uint32_t hb = lane >> 4, l7 = lane & 7;

    float* dtab = (float*)(sb + OFF_DTAB);
    float* km_s = (float*)(sb + OFF_KM);
    float* qm_s = (float*)(sb + OFF_QM);
    float* pm   = (float*)(sb + OFF_PM);
    float* pse  = (float*)(sb + OFF_PSE);
    float* psc  = (float*)(sb + OFF_PSC);
    float* redw = (float*)(sb + OFF_RED);

    const float araw  = __ldg(alpha_raw);
    const float alpha = fmaxf(araw, 0.0f) + log1pf(expf(-fabsf(araw)));
    dtab[tid] = expf(-alpha * (float)tid);
    km_s[tid] = k_mask[j * S_DIM + tid];
    if (tid < 128) qm_s[tid] = q_mask[i * S_DIM + mtile * 128 + tid];

    const char* qsrc = (const char*)(g_qh + ((size_t)i * S_DIM + mtile * 128) * H_DIM);
    const char* ksrc = (const char*)(g_kh + (size_t)j * S_DIM * H_DIM);

    // prologue: chunks 0..2 into stages 0..2
    #pragma unroll
    for (int c = 0; c < NSTAGE; c++) {
        load_stage(sbu + c * STAGE_STRIDE + OFF_Q, sbu + c * STAGE_STRIDE + OFF_K,
                   qsrc + c * 128, ksrc + c * 128, tid);
        CP_COMMIT();
    }

    float acc[2][16][4];
    #pragma unroll
    for (int a = 0; a < 2; a++)
        #pragma unroll
        for (int b = 0; b < 16; b++)
            #pragma unroll
            for (int c = 0; c < 4; c++) acc[a][b][c] = 0.0f;

    const uint32_t arow_off0 = (warp_m * 32 + (lane & 15)) * 128;
    const uint32_t brow_off  = (warp_n * 128 + gid) * 128;

    for (int c = 0; c < NCHUNK; c++) {
        if (c < NCHUNK - 2) CP_WAIT(2);
        else if (c == NCHUNK - 2) CP_WAIT(1);
        else CP_WAIT(0);
        __syncthreads();
        const uint32_t st = sbu + (uint32_t)(c % NSTAGE) * STAGE_STRIDE;
        compute_chunk(st + OFF_Q, st + OFF_K, acc,
                      arow_off0, hb, l7, brow_off, gid, tig);
        if (c + NSTAGE < NCHUNK) {
            __syncthreads();
            const int boff = (c + NSTAGE) * 128;
            load_stage(st + OFF_Q, st + OFF_K, qsrc + boff, ksrc + boff, tid);
            CP_COMMIT();
        }
    }

    // ---------------- epilogue: per-row softmax over t ----------------
    #pragma unroll
    for (int mf = 0; mf < 2; mf++) {
        #pragma unroll
        for (int h = 0; h < 2; h++) {
            const int row_local = warp_m * 32 + mf * 16 + h * 8 + (int)gid;
            const int s_glob = mtile * 128 + row_local;
            const float qmr = qm_s[row_local];

            float lg[32];
            float mx = -3.0e38f;
            #pragma unroll
            for (int nf = 0; nf < 16; nf++) {
                #pragma unroll
                for (int dc = 0; dc < 2; dc++) {
                    const int t = warp_n * 128 + nf * 8 + 2 * (int)tig + dc;
                    const float v = acc[mf][nf][h * 2 + dc];
                    const float valid = qmr * km_s[t];
                    int d = s_glob - t; d = d < 0 ? -d : d;
                    const float lv = v * dtab[d] * valid - (1.0f - valid) * 1e9f;
                    lg[nf * 2 + dc] = lv;
                    mx = fmaxf(mx, lv);
                }
            }
            mx = fmaxf(mx, __shfl_xor_sync(0xffffffffu, mx, 1));
            mx = fmaxf(mx, __shfl_xor_sync(0xffffffffu, mx, 2));
            float se = 0.0f, sc = 0.0f;
            #pragma unroll
            for (int nf = 0; nf < 16; nf++) {
                #pragma unroll
                for (int dc = 0; dc < 2; dc++) {
                    const float e = __expf(lg[nf * 2 + dc] - mx);
                    se += e;
                    sc = fmaf(e, acc[mf][nf][h * 2 + dc], sc);
                }
            }
            #pragma unroll
            for (int o = 1; o <= 2; o <<= 1) {
                se += __shfl_xor_sync(0xffffffffu, se, o);
                sc += __shfl_xor_sync(0xffffffffu, sc, o);
            }
            if (tig == 0) {
                pm [warp_n * 128 + row_local] = mx;
                pse[warp_n * 128 + row_local] = se;
                psc[warp_n * 128 + row_local] = sc;
            }
        }
    }
    __syncthreads();

    float score = 0.0f;
    if (tid < 128) {
        const float m0 = pm[tid],        m1 = pm[128 + tid];
        const float nm = fmaxf(m0, m1);
        const float e0 = __expf(m0 - nm), e1 = __expf(m1 - nm);
        const float S  = pse[tid] * e0 + pse[128 + tid] * e1;
        const float C  = psc[tid] * e0 + psc[128 + tid] * e1;
        score = qm_s[tid] * (C / S);
    }
    #pragma unroll
    for (int o = 16; o; o >>= 1) score += __shfl_xor_sync(0xffffffffu, score, o);
    if (lane == 0) redw[wid] = score;
    __syncthreads();
    if (tid == 0) {
        float tot = 0.0f;
        #pragma unroll
        for (int w = 0; w < 8; w++) tot += redw[w];
        g_part[(i * J_DIM + j) * 2 + mtile] = tot;
    }
}

// --------------------------------------------------------------- final reduce
// 4 blocks x 256 threads; each block covers 8 consecutive i values (256 pairs).
// Denominators computed once per block by the first 8 warps (one i per warp).
__global__ void reduce_kernel(const float* __restrict__ q_mask, float* __restrict__ out) {
    __shared__ float dsh[8];
    const int tid = threadIdx.x;
    const int wid = tid >> 5, lane = tid & 31;
    const int i0 = blockIdx.x * 8;

    // warp w: denom for i = i0 + w
    {
        const float* qm = q_mask + (i0 + wid) * S_DIM;
        float s = 0.0f;
        #pragma unroll
        for (int e = 0; e < 8; e++) s += qm[lane + e * 32];
        #pragma unroll
        for (int o = 16; o; o >>= 1) s += __shfl_xor_sync(0xffffffffu, s, o);
        if (lane == 0) dsh[wid] = fmaxf(s, 1.0f);
    }
    __syncthreads();

    const int idx = blockIdx.x * 256 + tid;       // global (i,j) index
    const float dn = dsh[tid >> 5];               // tid/32 == local i
    out[idx] = (g_part[idx * 2] + g_part[idx * 2 + 1]) / dn;
}

// -------------------------------------------------------------------- launch
extern "C" void kernel_launch(void* const* d_in, const int* in_sizes, int n_in,
                              void* d_out, int out_size) {
    const float* q  = (const float*)d_in[0];
    const float* k  = (const float*)d_in[1];
    const float* qm = (const float*)d_in[2];
    const float* km = (const float*)d_in[3];
    const float* ar = (const float*)d_in[4];
    float* out = (float*)d_out;

    norm_kernel<<<I_DIM * S_DIM, 256>>>(q, 0);
    norm_kernel<<<J_DIM * S_DIM, 256>>>(k, 1);

    static int smem_set = 0;
    if (!smem_set) {
        cudaFuncSetAttribute(pair_kernel, cudaFuncAttributeMaxDynamicSharedMemorySize, SMEM_DYN);
        smem_set = 1;
    }
    dim3 grid(2, J_DIM, I_DIM);
    pair_kernel<<<grid, NTH, SMEM_DYN>>>(qm, km, ar);

    reduce_kernel<<<4, 256>>>(qm, out);
}